// round 13
// baseline (speedup 1.0000x reference)
#include <cuda_runtime.h>
#include <math.h>

#define NBOX 256
#define BMAX 16

#define PLANE0 6400   // 80*80
#define PLANE1 1600   // 40*40
#define PLANE2 400    // 20*20
#define MOFF0 0
#define MOFF1 (16*PLANE0)            // 102400
#define MOFF2 (MOFF1 + 16*PLANE1)    // 128000
#define MTOT  (MOFF2 + 16*PLANE2)    // 134400

// reduce tiles: every thread streams CCHUNK=8 float4 pairs (256B)
#define CCHUNK 8
#define RBLK0 1600
#define RBLK1 800
#define RBLK2 400
#define RBLK_TOT (RBLK0 + RBLK1 + RBLK2)   // 2800

#define CH 24   // boxes per smem chunk in prep

// Scratch (allocation-free: __device__ globals)
__device__ __align__(16) float  g_mask[MTOT];
__device__ double g_summ_part[48];   // [level*16 + b]
__device__ double g_sse[3];
__device__ int    g_done;

// ---------------------------------------------------------------------------
__device__ __forceinline__ float block_reduce_sum(float v) {
    __shared__ float sh[8];
    #pragma unroll
    for (int off = 16; off > 0; off >>= 1)
        v += __shfl_down_sync(0xffffffffu, v, off);
    int lane = threadIdx.x & 31;
    int wid  = threadIdx.x >> 5;
    if (lane == 0) sh[wid] = v;
    __syncthreads();
    if (wid == 0) {
        v = (lane < 8) ? sh[lane] : 0.0f;
        #pragma unroll
        for (int off = 4; off > 0; off >>= 1)
            v += __shfl_down_sync(0xffffffffu, v, off);
    }
    return v;  // valid in thread 0
}

// ---------------------------------------------------------------------------
// Fully fused prologue: one block per (level, batch). Builds the batch's box
// list, computes per-box separable 1-D gaussian tables in smem (denominator
// STD^2*(w/2)^2 = w^2 for STD=2), folds them into the smem plane mask, writes
// g_mask + per-block sum(m) partial. Block 0 also inits g_sse / g_done.
__global__ void __launch_bounds__(256)
prep_mask_kernel(const float* __restrict__ bboxes, const int* __restrict__ bidx) {
    __shared__ float s_plane[PLANE0];          // 25.6 KB (worst case level 0)
    __shared__ float s_ex[CH * 80];            // 7.7 KB
    __shared__ float s_ey[CH * 80];            // 7.7 KB
    __shared__ float s_prm[CH][8];             // xc,yc,wd,ht,xl,xr,yt,yd
    __shared__ int   s_list[NBOX];
    __shared__ int   s_cnt;

    int level = blockIdx.x >> 4;
    int b     = blockIdx.x & 15;
    int S     = 80 >> level;                   // 80 / 40 / 20
    int plane = S * S;
    int tid   = threadIdx.x;

    if (tid == 0) s_cnt = 0;
    if (blockIdx.x == 0) {
        if (tid < 3) g_sse[tid] = 0.0;
        if (tid == 3) g_done = 0;
    }
    __syncthreads();

    // box list for this batch (order irrelevant: max is commutative)
    if (bidx[tid] == b) {
        int slot = atomicAdd(&s_cnt, 1);
        s_list[slot] = tid;
    }
    for (int i = tid; i < plane; i += 256) s_plane[i] = 0.0f;
    __syncthreads();
    int cnt = s_cnt;

    for (int c0 = 0; c0 < cnt; c0 += CH) {
        int ch = min(CH, cnt - c0);
        // per-box params
        if (tid < ch) {
            float4 bb = reinterpret_cast<const float4*>(bboxes)[s_list[c0 + tid]];
            float fS = (float)S;
            int S1 = S - 1;
            int xc = (int)floorf(bb.x * fS);
            int yc = (int)floorf(bb.y * fS);
            int w  = (int)floorf(bb.z * fS);
            int h  = (int)floorf(bb.w * fS);
            int xl = max(xc - w / 2, 0);
            int xr = min(xc + w / 2, S1);
            int yt = max(yc - h / 2, 0);
            int yd = min(yc + h / 2, S1);
            s_prm[tid][0] = (float)xc;
            s_prm[tid][1] = (float)yc;
            s_prm[tid][2] = (float)(xr - xl + 1);
            s_prm[tid][3] = (float)(yd - yt + 1);
            s_prm[tid][4] = (float)xl;
            s_prm[tid][5] = (float)xr;
            s_prm[tid][6] = (float)yt;
            s_prm[tid][7] = (float)yd;
        }
        __syncthreads();
        // 1-D tables for this chunk
        for (int i = tid; i < ch * S; i += 256) {
            int k = i / S;
            int x = i - k * S;
            float fx = (float)x;
            float dx = fx - s_prm[k][0];
            float dy = fx - s_prm[k][1];
            float wd = s_prm[k][2];
            float ht = s_prm[k][3];
            float exv = (fx >= s_prm[k][4] && fx <= s_prm[k][5])
                        ? expf(-(dx * dx) / (wd * wd)) : 0.0f;
            float eyv = (fx >= s_prm[k][6] && fx <= s_prm[k][7])
                        ? expf(-(dy * dy) / (ht * ht)) : 0.0f;
            s_ex[k * S + x] = exv;
            s_ey[k * S + x] = eyv;
        }
        __syncthreads();
        // fold chunk into plane mask (float4 across x)
        int plane4 = plane >> 2;
        for (int i4 = tid; i4 < plane4; i4 += 256) {
            int pix = i4 * 4;
            int y   = pix / S;
            int x0  = pix - y * S;
            float4 mp = reinterpret_cast<float4*>(s_plane)[i4];
            for (int k = 0; k < ch; k++) {
                float4 exv = *reinterpret_cast<float4*>(&s_ex[k * S + x0]);
                float  eyv = s_ey[k * S + y];
                mp.x = fmaxf(mp.x, exv.x * eyv);
                mp.y = fmaxf(mp.y, exv.y * eyv);
                mp.z = fmaxf(mp.z, exv.z * eyv);
                mp.w = fmaxf(mp.w, exv.w * eyv);
            }
            reinterpret_cast<float4*>(s_plane)[i4] = mp;
        }
        __syncthreads();
    }

    // write out + per-block sum(m)
    int moff = (level == 0) ? MOFF0 : (level == 1) ? MOFF1 : MOFF2;
    float acc = 0.0f;
    for (int i = tid; i < plane; i += 256) {
        float v = s_plane[i];
        g_mask[moff + b * plane + i] = v;
        acc += v;
    }
    float bs = block_reduce_sum(acc);
    if (tid == 0) g_summ_part[level * 16 + b] = (double)bs;
}

// ---------------------------------------------------------------------------
// HBM-bound reduction. Each thread owns a fixed (b, j4) mask float4 (one
// __ldg, L2-resident, reused nsplit x across the grid) and streams CCHUNK=8
// channels of p/t with explicit batch-of-4 pair loads, __ldcs (read-once).
template<int C, int S, int LEVEL, int MOFF>
__device__ __forceinline__ void reduce_body(const float4* __restrict__ p,
                                            const float4* __restrict__ t,
                                            int blk) {
    constexpr int PLANE4 = S * S / 4;
    constexpr int nsplit = C / CCHUNK;
    constexpr int per_b  = PLANE4 * nsplit;
    int idx = blk * 256 + threadIdx.x;
    int b  = idx / per_b;
    int r  = idx - b * per_b;
    int sp = r / PLANE4;
    int j  = r - sp * PLANE4;

    int base = (b * C + sp * CCHUNK) * PLANE4 + j;
    const float4* m = reinterpret_cast<const float4*>(g_mask + MOFF);

    // mask load first; arrives while the first stream batch is in flight
    float4 mv = __ldg(&m[b * PLANE4 + j]);

    float4 pv[4], tv[4];
    #pragma unroll
    for (int u = 0; u < 4; u++) pv[u] = __ldcs(p + base + u * PLANE4);
    #pragma unroll
    for (int u = 0; u < 4; u++) tv[u] = __ldcs(t + base + u * PLANE4);

    float acc0 = 0.0f, acc1 = 0.0f;
    #pragma unroll
    for (int cc = 0; cc < CCHUNK; cc += 4) {
        if (cc > 0) {
            base += 4 * PLANE4;
            #pragma unroll
            for (int u = 0; u < 4; u++) pv[u] = __ldcs(p + base + u * PLANE4);
            #pragma unroll
            for (int u = 0; u < 4; u++) tv[u] = __ldcs(t + base + u * PLANE4);
        }
        #pragma unroll
        for (int u = 0; u < 4; u++) {
            float d0 = (pv[u].x - tv[u].x) * mv.x;
            float d1 = (pv[u].y - tv[u].y) * mv.y;
            float d2 = (pv[u].z - tv[u].z) * mv.z;
            float d3 = (pv[u].w - tv[u].w) * mv.w;
            acc0 += d0 * d0 + d1 * d1;
            acc1 += d2 * d2 + d3 * d3;
        }
    }

    float acc = block_reduce_sum(acc0 + acc1);
    if (threadIdx.x == 0) atomicAdd(&g_sse[LEVEL], (double)acc);
}

// Levels packed by traffic share: [0,1600) L0, [1600,2400) L1, [2400,2800) L2.
// Fused epilogue in the last-finishing block via done-counter.
__global__ void __launch_bounds__(256, 4)
reduce_all_kernel(const float4* __restrict__ p0, const float4* __restrict__ t0,
                  const float4* __restrict__ p1, const float4* __restrict__ t1,
                  const float4* __restrict__ p2, const float4* __restrict__ t2,
                  float* __restrict__ out) {
    int blk = blockIdx.x;
    if (blk < RBLK0)               reduce_body<128, 80, 0, MOFF0>(p0, t0, blk);
    else if (blk < RBLK0 + RBLK1)  reduce_body<256, 40, 1, MOFF1>(p1, t1, blk - RBLK0);
    else                           reduce_body<512, 20, 2, MOFF2>(p2, t2, blk - RBLK0 - RBLK1);

    if (threadIdx.x == 0) {
        __threadfence();
        int v = atomicAdd(&g_done, 1);
        if (v == RBLK_TOT - 1) {
            volatile double* sse  = g_sse;
            volatile double* sp   = g_summ_part;
            double tot = 0.0;
            const double Cs[3] = {128.0, 256.0, 512.0};
            #pragma unroll
            for (int l = 0; l < 3; l++) {
                double sm = 0.0;
                for (int q = 0; q < 16; q++) sm += sp[l * 16 + q];
                tot += sse[l] / (Cs[l] * sm);
            }
            out[0] = (float)(tot / 3.0);
        }
    }
}

// ---------------------------------------------------------------------------
extern "C" void kernel_launch(void* const* d_in, const int* in_sizes, int n_in,
                              void* d_out, int out_size) {
    // metadata order (interleaved): 0:y_pred0 1:y_true0 2:y_pred1 3:y_true1
    // 4:y_pred2 5:y_true2 6:bboxes 7:cls 8:batch_idx
    const float* p0 = (const float*)d_in[0];
    const float* t0 = (const float*)d_in[1];
    const float* p1 = (const float*)d_in[2];
    const float* t1 = (const float*)d_in[3];
    const float* p2 = (const float*)d_in[4];
    const float* t2 = (const float*)d_in[5];
    const float* bboxes = (const float*)d_in[6];
    const int*   bidx   = (const int*)d_in[8];
    float* out = (float*)d_out;

    prep_mask_kernel<<<48, 256>>>(bboxes, bidx);
    reduce_all_kernel<<<RBLK_TOT, 256>>>((const float4*)p0, (const float4*)t0,
                                         (const float4*)p1, (const float4*)t1,
                                         (const float4*)p2, (const float4*)t2,
                                         out);
}

// round 14
// speedup vs baseline: 1.0333x; 1.0333x over previous
#include <cuda_runtime.h>
#include <math.h>

#define NBOX 256
#define BMAX 16

#define PLANE0 6400   // 80*80
#define PLANE1 1600   // 40*40
#define PLANE2 400    // 20*20
#define MOFF0 0
#define MOFF1 (16*PLANE0)            // 102400
#define MOFF2 (MOFF1 + 16*PLANE1)    // 128000
#define MTOT  (MOFF2 + 16*PLANE2)    // 134400

// mask_final blocks (256 threads each)
#define MBLK0 (16*PLANE0/256)   // 400
#define MBLK1 (16*PLANE1/256)   // 100
#define MBLK2 (16*PLANE2/256)   // 25
#define MBLK_TOT (MBLK0+MBLK1+MBLK2)  // 525

// stream: every thread streams CCHUNK=8 float4 pairs (256B)
#define CCHUNK 8
#define RBLK0 1600
#define RBLK1 800
#define RBLK2 400
#define RBLK_TOT (RBLK0 + RBLK1 + RBLK2)   // 2800

// Scratch (allocation-free: __device__ globals; zero-init at load, and every
// kernel_launch invocation restores them to zero => graph replays are valid).
__device__ __align__(16) float  g_acc[MTOT];   // per-pixel sum_c (p-t)^2
__device__ __align__(16) float  g_ex[3][NBOX * 80];
__device__ __align__(16) float  g_ey[3][NBOX * 80];
__device__ int    g_list[BMAX * NBOX];
__device__ int    g_cnt[BMAX];
__device__ double g_sse[3];
__device__ double g_summ[3];
__device__ int    g_done;

// ---------------------------------------------------------------------------
// Kernel A (runs FIRST, absorbs clock ramp; no dependencies): pure HBM
// stream. Each thread owns a fixed (b, j4) float4 of pixels, streams CCHUNK
// channels of p/t with batched loads, and REDs its 4 per-component partials
// of sum_c (p-t)^2 into g_acc. Mask applied later as m^2 * g_acc.
template<int C, int S, int MOFF>
__device__ __forceinline__ void stream_body(const float4* __restrict__ p,
                                            const float4* __restrict__ t,
                                            int blk) {
    constexpr int PLANE4 = S * S / 4;
    constexpr int nsplit = C / CCHUNK;
    constexpr int per_b  = PLANE4 * nsplit;
    int idx = blk * 256 + threadIdx.x;
    int b  = idx / per_b;
    int r  = idx - b * per_b;
    int sp = r / PLANE4;
    int j  = r - sp * PLANE4;

    int base = (b * C + sp * CCHUNK) * PLANE4 + j;

    float4 pv[4], tv[4];
    #pragma unroll
    for (int u = 0; u < 4; u++) pv[u] = __ldcs(p + base + u * PLANE4);
    #pragma unroll
    for (int u = 0; u < 4; u++) tv[u] = __ldcs(t + base + u * PLANE4);

    float a0 = 0.0f, a1 = 0.0f, a2 = 0.0f, a3 = 0.0f;
    #pragma unroll
    for (int cc = 0; cc < CCHUNK; cc += 4) {
        if (cc > 0) {
            base += 4 * PLANE4;
            #pragma unroll
            for (int u = 0; u < 4; u++) pv[u] = __ldcs(p + base + u * PLANE4);
            #pragma unroll
            for (int u = 0; u < 4; u++) tv[u] = __ldcs(t + base + u * PLANE4);
        }
        #pragma unroll
        for (int u = 0; u < 4; u++) {
            float d0 = pv[u].x - tv[u].x;
            float d1 = pv[u].y - tv[u].y;
            float d2 = pv[u].z - tv[u].z;
            float d3 = pv[u].w - tv[u].w;
            a0 += d0 * d0;
            a1 += d1 * d1;
            a2 += d2 * d2;
            a3 += d3 * d3;
        }
    }

    float* dst = g_acc + MOFF + (b * PLANE4 + j) * 4;
    atomicAdd(dst + 0, a0);
    atomicAdd(dst + 1, a1);
    atomicAdd(dst + 2, a2);
    atomicAdd(dst + 3, a3);
}

__global__ void __launch_bounds__(256, 4)
stream_kernel(const float4* __restrict__ p0, const float4* __restrict__ t0,
              const float4* __restrict__ p1, const float4* __restrict__ t1,
              const float4* __restrict__ p2, const float4* __restrict__ t2) {
    int blk = blockIdx.x;
    if (blk < RBLK0)               stream_body<128, 80, MOFF0>(p0, t0, blk);
    else if (blk < RBLK0 + RBLK1)  stream_body<256, 40, MOFF1>(p1, t1, blk - RBLK0);
    else                           stream_body<512, 20, MOFF2>(p2, t2, blk - RBLK0 - RBLK1);
}

// ---------------------------------------------------------------------------
// Kernel B: per-box separable gaussian tables (blocks 0..767; level=blk>>8,
// box=blk&255) + block 768: zero accumulators + parallel per-batch box lists.
// gauss = exp(-tx)*exp(-ty), denom = STD^2*(w/2)^2 = w^2 for STD=2.
__global__ void setup_kernel(const float* __restrict__ bboxes,
                             const int* __restrict__ bidx) {
    int blk = blockIdx.x;
    if (blk < 768) {
        int level = blk >> 8;
        int n = blk & 255;
        int S = 80 >> level;
        int x = threadIdx.x;
        if (x >= S) return;
        float4 bb = reinterpret_cast<const float4*>(bboxes)[n];
        float fS = (float)S;
        int S1 = S - 1;
        int xc = (int)floorf(bb.x * fS);
        int yc = (int)floorf(bb.y * fS);
        int w  = (int)floorf(bb.z * fS);
        int h  = (int)floorf(bb.w * fS);
        int xl = max(xc - w / 2, 0);
        int xr = min(xc + w / 2, S1);
        int yt = max(yc - h / 2, 0);
        int yd = min(yc + h / 2, S1);
        float wd = (float)(xr - xl + 1);
        float ht = (float)(yd - yt + 1);
        float fx = (float)x;
        float dx = fx - (float)xc;
        float dy = fx - (float)yc;
        float tx = (dx * dx) / (wd * wd);
        float ty = (dy * dy) / (ht * ht);
        g_ex[level][n * S + x] = (x >= xl && x <= xr) ? expf(-tx) : 0.0f;
        g_ey[level][n * S + x] = (x >= yt && x <= yd) ? expf(-ty) : 0.0f;
    } else {
        int t = threadIdx.x;
        if (t < BMAX) g_cnt[t] = 0;
        if (t < 3) { g_sse[t] = 0.0; g_summ[t] = 0.0; }
        __syncthreads();
        int b = bidx[t];
        int slot = atomicAdd(&g_cnt[b], 1);
        g_list[b * NBOX + slot] = t;
    }
}

// ---------------------------------------------------------------------------
// dual block reduction (one shared pass, one __syncthreads)
__device__ __forceinline__ void block_reduce_sum2(float& a, float& b) {
    __shared__ float sha[8], shb[8];
    #pragma unroll
    for (int off = 16; off > 0; off >>= 1) {
        a += __shfl_down_sync(0xffffffffu, a, off);
        b += __shfl_down_sync(0xffffffffu, b, off);
    }
    int lane = threadIdx.x & 31;
    int wid  = threadIdx.x >> 5;
    if (lane == 0) { sha[wid] = a; shb[wid] = b; }
    __syncthreads();
    if (wid == 0) {
        a = (lane < 8) ? sha[lane] : 0.0f;
        b = (lane < 8) ? shb[lane] : 0.0f;
        #pragma unroll
        for (int off = 4; off > 0; off >>= 1) {
            a += __shfl_down_sync(0xffffffffu, a, off);
            b += __shfl_down_sync(0xffffffffu, b, off);
        }
    }
}

// ---------------------------------------------------------------------------
// Kernel C: mask + final. Per pixel: m = max over this batch's boxes of
// ex*ey; sse += m^2 * g_acc[pix]; summ += m. Zeroes its g_acc chunk after
// use (restores state for graph replay). Last-finishing block computes out.
template<int S, int MOFF, int LEVEL>
__device__ __forceinline__ void final_body(int blk) {
    constexpr int plane = S * S;
    int i = blk * 256 + threadIdx.x;
    int b = i / plane;
    int r = i - b * plane;
    int y = r / S;
    int x = r - y * S;
    int cnt = g_cnt[b];
    const int*   lst = &g_list[b * NBOX];
    const float* ex  = g_ex[LEVEL];
    const float* ey  = g_ey[LEVEL];
    float acc_i = g_acc[MOFF + i];     // load early, latency hidden by mask loop
    float m = 0.0f;
    for (int k = 0; k < cnt; k++) {
        int n = lst[k];
        m = fmaxf(m, ex[n * S + x] * ey[n * S + y]);
    }
    g_acc[MOFF + i] = 0.0f;            // restore for next replay
    float se = m * m * acc_i;
    float sm = m;
    block_reduce_sum2(se, sm);
    if (threadIdx.x == 0) {
        atomicAdd(&g_sse[LEVEL],  (double)se);
        atomicAdd(&g_summ[LEVEL], (double)sm);
    }
}

__global__ void mask_final_kernel(float* __restrict__ out) {
    int blk = blockIdx.x;
    if (blk < MBLK0)              final_body<80, MOFF0, 0>(blk);
    else if (blk < MBLK0 + MBLK1) final_body<40, MOFF1, 1>(blk - MBLK0);
    else                          final_body<20, MOFF2, 2>(blk - MBLK0 - MBLK1);

    if (threadIdx.x == 0) {
        __threadfence();
        int v = atomicAdd(&g_done, 1);
        if (v == MBLK_TOT - 1) {
            volatile double* sse  = g_sse;
            volatile double* summ = g_summ;
            double tot = sse[0] / (128.0 * summ[0])
                       + sse[1] / (256.0 * summ[1])
                       + sse[2] / (512.0 * summ[2]);
            out[0] = (float)(tot / 3.0);
            g_done = 0;                // restore for next replay
        }
    }
}

// ---------------------------------------------------------------------------
extern "C" void kernel_launch(void* const* d_in, const int* in_sizes, int n_in,
                              void* d_out, int out_size) {
    // metadata order (interleaved): 0:y_pred0 1:y_true0 2:y_pred1 3:y_true1
    // 4:y_pred2 5:y_true2 6:bboxes 7:cls 8:batch_idx
    const float* p0 = (const float*)d_in[0];
    const float* t0 = (const float*)d_in[1];
    const float* p1 = (const float*)d_in[2];
    const float* t1 = (const float*)d_in[3];
    const float* p2 = (const float*)d_in[4];
    const float* t2 = (const float*)d_in[5];
    const float* bboxes = (const float*)d_in[6];
    const int*   bidx   = (const int*)d_in[8];
    float* out = (float*)d_out;

    // Big stream first (no dependencies) so clock ramp is absorbed there.
    stream_kernel<<<RBLK_TOT, 256>>>((const float4*)p0, (const float4*)t0,
                                     (const float4*)p1, (const float4*)t1,
                                     (const float4*)p2, (const float4*)t2);
    setup_kernel<<<769, 256>>>(bboxes, bidx);
    mask_final_kernel<<<MBLK_TOT, 256>>>(out);
}

// round 15
// speedup vs baseline: 1.0385x; 1.0050x over previous
#include <cuda_runtime.h>
#include <math.h>

#define NBOX 256
#define BMAX 16

#define PLANE0 6400   // 80*80
#define PLANE1 1600   // 40*40
#define PLANE2 400    // 20*20
#define MOFF0 0
#define MOFF1 (16*PLANE0)            // 102400
#define MOFF2 (MOFF1 + 16*PLANE1)    // 128000
#define MTOT  (MOFF2 + 16*PLANE2)    // 134400

// mask_final blocks (256 threads each)
#define MBLK0 (16*PLANE0/256)   // 400
#define MBLK1 (16*PLANE1/256)   // 100
#define MBLK2 (16*PLANE2/256)   // 25
#define MBLK_TOT (MBLK0+MBLK1+MBLK2)  // 525

// stream: every thread streams CCHUNK=8 float4 pairs (256B)
#define CCHUNK 8
#define RBLK0 1600
#define RBLK1 800
#define RBLK2 400
#define RBLK_TOT (RBLK0 + RBLK1 + RBLK2)   // 2800

// Scratch (allocation-free: __device__ globals; zero-init at load, and every
// kernel_launch invocation restores them to zero => graph replays are valid).
__device__ __align__(16) float  g_acc[MTOT];   // per-pixel sum_c (p-t)^2
__device__ __align__(16) float  g_ex[3][NBOX * 80];
__device__ __align__(16) float  g_ey[3][NBOX * 80];
__device__ int    g_list[BMAX * NBOX];
__device__ int    g_cnt[BMAX];
__device__ double g_sse[3];
__device__ double g_summ[3];
__device__ int    g_done;

// ---------------------------------------------------------------------------
// Kernel 1 (runs FIRST, absorbs fixed first-node overhead; independent of the
// stream): per-box separable gaussian tables (blocks 0..767; level=blk>>8,
// box=blk&255) + block 768: zero scalar accumulators + per-batch box lists.
// gauss = exp(-tx)*exp(-ty), denom = STD^2*(w/2)^2 = w^2 for STD=2.
__global__ void setup_kernel(const float* __restrict__ bboxes,
                             const int* __restrict__ bidx) {
    int blk = blockIdx.x;
    if (blk < 768) {
        int level = blk >> 8;
        int n = blk & 255;
        int S = 80 >> level;
        int x = threadIdx.x;
        if (x >= S) return;
        float4 bb = reinterpret_cast<const float4*>(bboxes)[n];
        float fS = (float)S;
        int S1 = S - 1;
        int xc = (int)floorf(bb.x * fS);
        int yc = (int)floorf(bb.y * fS);
        int w  = (int)floorf(bb.z * fS);
        int h  = (int)floorf(bb.w * fS);
        int xl = max(xc - w / 2, 0);
        int xr = min(xc + w / 2, S1);
        int yt = max(yc - h / 2, 0);
        int yd = min(yc + h / 2, S1);
        float wd = (float)(xr - xl + 1);
        float ht = (float)(yd - yt + 1);
        float fx = (float)x;
        float dx = fx - (float)xc;
        float dy = fx - (float)yc;
        float tx = (dx * dx) / (wd * wd);
        float ty = (dy * dy) / (ht * ht);
        g_ex[level][n * S + x] = (x >= xl && x <= xr) ? expf(-tx) : 0.0f;
        g_ey[level][n * S + x] = (x >= yt && x <= yd) ? expf(-ty) : 0.0f;
    } else {
        int t = threadIdx.x;
        if (t < BMAX) g_cnt[t] = 0;
        if (t < 3) { g_sse[t] = 0.0; g_summ[t] = 0.0; }
        __syncthreads();
        int b = bidx[t];
        int slot = atomicAdd(&g_cnt[b], 1);
        g_list[b * NBOX + slot] = t;
    }
}

// ---------------------------------------------------------------------------
// Kernel 2: pure HBM stream. Each thread owns a fixed (b, j4) float4 of
// pixels, streams CCHUNK channels of p/t with batched loads, and REDs its 4
// per-component partials of sum_c (p-t)^2 into g_acc. Mask applied later as
// m^2 * g_acc (exact: sum_c (m*(p-t))^2 = m^2 * sum_c (p-t)^2).
template<int C, int S, int MOFF>
__device__ __forceinline__ void stream_body(const float4* __restrict__ p,
                                            const float4* __restrict__ t,
                                            int blk) {
    constexpr int PLANE4 = S * S / 4;
    constexpr int nsplit = C / CCHUNK;
    constexpr int per_b  = PLANE4 * nsplit;
    int idx = blk * 256 + threadIdx.x;
    int b  = idx / per_b;
    int r  = idx - b * per_b;
    int sp = r / PLANE4;
    int j  = r - sp * PLANE4;

    int base = (b * C + sp * CCHUNK) * PLANE4 + j;

    float4 pv[4], tv[4];
    #pragma unroll
    for (int u = 0; u < 4; u++) pv[u] = __ldcs(p + base + u * PLANE4);
    #pragma unroll
    for (int u = 0; u < 4; u++) tv[u] = __ldcs(t + base + u * PLANE4);

    float a0 = 0.0f, a1 = 0.0f, a2 = 0.0f, a3 = 0.0f;
    #pragma unroll
    for (int cc = 0; cc < CCHUNK; cc += 4) {
        if (cc > 0) {
            base += 4 * PLANE4;
            #pragma unroll
            for (int u = 0; u < 4; u++) pv[u] = __ldcs(p + base + u * PLANE4);
            #pragma unroll
            for (int u = 0; u < 4; u++) tv[u] = __ldcs(t + base + u * PLANE4);
        }
        #pragma unroll
        for (int u = 0; u < 4; u++) {
            float d0 = pv[u].x - tv[u].x;
            float d1 = pv[u].y - tv[u].y;
            float d2 = pv[u].z - tv[u].z;
            float d3 = pv[u].w - tv[u].w;
            a0 += d0 * d0;
            a1 += d1 * d1;
            a2 += d2 * d2;
            a3 += d3 * d3;
        }
    }

    float* dst = g_acc + MOFF + (b * PLANE4 + j) * 4;
    atomicAdd(dst + 0, a0);
    atomicAdd(dst + 1, a1);
    atomicAdd(dst + 2, a2);
    atomicAdd(dst + 3, a3);
}

__global__ void __launch_bounds__(256, 4)
stream_kernel(const float4* __restrict__ p0, const float4* __restrict__ t0,
              const float4* __restrict__ p1, const float4* __restrict__ t1,
              const float4* __restrict__ p2, const float4* __restrict__ t2) {
    int blk = blockIdx.x;
    if (blk < RBLK0)               stream_body<128, 80, MOFF0>(p0, t0, blk);
    else if (blk < RBLK0 + RBLK1)  stream_body<256, 40, MOFF1>(p1, t1, blk - RBLK0);
    else                           stream_body<512, 20, MOFF2>(p2, t2, blk - RBLK0 - RBLK1);
}

// ---------------------------------------------------------------------------
// dual block reduction (one shared pass, one __syncthreads)
__device__ __forceinline__ void block_reduce_sum2(float& a, float& b) {
    __shared__ float sha[8], shb[8];
    #pragma unroll
    for (int off = 16; off > 0; off >>= 1) {
        a += __shfl_down_sync(0xffffffffu, a, off);
        b += __shfl_down_sync(0xffffffffu, b, off);
    }
    int lane = threadIdx.x & 31;
    int wid  = threadIdx.x >> 5;
    if (lane == 0) { sha[wid] = a; shb[wid] = b; }
    __syncthreads();
    if (wid == 0) {
        a = (lane < 8) ? sha[lane] : 0.0f;
        b = (lane < 8) ? shb[lane] : 0.0f;
        #pragma unroll
        for (int off = 4; off > 0; off >>= 1) {
            a += __shfl_down_sync(0xffffffffu, a, off);
            b += __shfl_down_sync(0xffffffffu, b, off);
        }
    }
}

// ---------------------------------------------------------------------------
// Kernel 3: mask + final. Per pixel: m = max over this batch's boxes of
// ex*ey; sse += m^2 * g_acc[pix]; summ += m. Zeroes its g_acc chunk after
// use (restores state for graph replay). Last-finishing block computes out.
template<int S, int MOFF, int LEVEL>
__device__ __forceinline__ void final_body(int blk) {
    constexpr int plane = S * S;
    int i = blk * 256 + threadIdx.x;
    int b = i / plane;
    int r = i - b * plane;
    int y = r / S;
    int x = r - y * S;
    int cnt = g_cnt[b];
    const int*   lst = &g_list[b * NBOX];
    const float* ex  = g_ex[LEVEL];
    const float* ey  = g_ey[LEVEL];
    float acc_i = g_acc[MOFF + i];     // load early, latency hidden by mask loop
    float m = 0.0f;
    for (int k = 0; k < cnt; k++) {
        int n = lst[k];
        m = fmaxf(m, ex[n * S + x] * ey[n * S + y]);
    }
    g_acc[MOFF + i] = 0.0f;            // restore for next replay
    float se = m * m * acc_i;
    float sm = m;
    block_reduce_sum2(se, sm);
    if (threadIdx.x == 0) {
        atomicAdd(&g_sse[LEVEL],  (double)se);
        atomicAdd(&g_summ[LEVEL], (double)sm);
    }
}

__global__ void mask_final_kernel(float* __restrict__ out) {
    int blk = blockIdx.x;
    if (blk < MBLK0)              final_body<80, MOFF0, 0>(blk);
    else if (blk < MBLK0 + MBLK1) final_body<40, MOFF1, 1>(blk - MBLK0);
    else                          final_body<20, MOFF2, 2>(blk - MBLK0 - MBLK1);

    if (threadIdx.x == 0) {
        __threadfence();
        int v = atomicAdd(&g_done, 1);
        if (v == MBLK_TOT - 1) {
            volatile double* sse  = g_sse;
            volatile double* summ = g_summ;
            double tot = sse[0] / (128.0 * summ[0])
                       + sse[1] / (256.0 * summ[1])
                       + sse[2] / (512.0 * summ[2]);
            out[0] = (float)(tot / 3.0);
            g_done = 0;                // restore for next replay
        }
    }
}

// ---------------------------------------------------------------------------
extern "C" void kernel_launch(void* const* d_in, const int* in_sizes, int n_in,
                              void* d_out, int out_size) {
    // metadata order (interleaved): 0:y_pred0 1:y_true0 2:y_pred1 3:y_true1
    // 4:y_pred2 5:y_true2 6:bboxes 7:cls 8:batch_idx
    const float* p0 = (const float*)d_in[0];
    const float* t0 = (const float*)d_in[1];
    const float* p1 = (const float*)d_in[2];
    const float* t1 = (const float*)d_in[3];
    const float* p2 = (const float*)d_in[4];
    const float* t2 = (const float*)d_in[5];
    const float* bboxes = (const float*)d_in[6];
    const int*   bidx   = (const int*)d_in[8];
    float* out = (float*)d_out;

    // Tiny independent kernel first: absorbs the fixed first-node overhead.
    setup_kernel<<<769, 256>>>(bboxes, bidx);
    stream_kernel<<<RBLK_TOT, 256>>>((const float4*)p0, (const float4*)t0,
                                     (const float4*)p1, (const float4*)t1,
                                     (const float4*)p2, (const float4*)t2);
    mask_final_kernel<<<MBLK_TOT, 256>>>(out);
}